// round 4
// baseline (speedup 1.0000x reference)
#include <cuda_runtime.h>
#include <cuda_fp16.h>

// Problem constants (shape-specialized)
#define NN 50000       // nodes
#define NE 800000      // edges
#define IND 128        // input dim
#define FD  256        // HEADS*HID
#define HID 64
#define NG  64         // graphs
#define NC  10         // classes
#define SLOPE 0.2f

// ---------------- device scratch (no allocations allowed) ----------------
__device__ float    g_featB[NN * FD];     // aggregated layer-1 output (GEMM2 input, fp32)
__device__ __half2  g_featH[NN * FD / 2]; // projected features, fp16 pairs (gather table)
__device__ float    g_el[NN * 4];
__device__ float    g_er[NN * 4];
__device__ int      g_rowptr[NN + 1];
__device__ int      g_cnt[NN];
__device__ int      g_esrc[NE];           // src node id, sorted by dst (CSR)
__device__ unsigned g_pool[NG * HID];     // ordered-uint max-pool accumulator

// ---------------- helpers ----------------
__device__ __forceinline__ unsigned f2ord(float f) {
    unsigned u = __float_as_uint(f);
    return (u >> 31) ? ~u : (u | 0x80000000u);
}
__device__ __forceinline__ float ord2f(unsigned u) {
    return (u >> 31) ? __uint_as_float(u & 0x7fffffffu) : __uint_as_float(~u);
}
__device__ __forceinline__ float lrelu(float x) { return x > 0.f ? x : SLOPE * x; }

__device__ __forceinline__ unsigned f2tf32(float x) {
    unsigned r;
    asm("cvt.rna.tf32.f32 %0, %1;" : "=r"(r) : "f"(x));
    return r;
}
__device__ __forceinline__ void mma_tf32(float c[4], const unsigned a[4], const unsigned b[2]) {
    asm volatile(
        "mma.sync.aligned.m16n8k8.row.col.f32.tf32.tf32.f32 "
        "{%0,%1,%2,%3}, {%4,%5,%6,%7}, {%8,%9}, {%0,%1,%2,%3};"
        : "+f"(c[0]), "+f"(c[1]), "+f"(c[2]), "+f"(c[3])
        : "r"(a[0]), "r"(a[1]), "r"(a[2]), "r"(a[3]), "r"(b[0]), "r"(b[1]));
}

// ---------------- fused tf32 GEMM + attention coefficients ----------------
// feat = A[M,K] @ B[K,256] (tf32, fp32 acc). Output written ONLY as fp16 pairs
// to g_featH; el/er written fp32. Block tile 128x256 (full width), BK=16,
// 8 warps of 64x64; warp-col == head.
template <int K>
__global__ __launch_bounds__(256) void gemm_attn_kernel(const float* __restrict__ A,
                                                        const float* __restrict__ B,
                                                        const float* __restrict__ al,
                                                        const float* __restrict__ ar)
{
    __shared__ unsigned As[128 * 17];   // [m][k], stride 17
    __shared__ unsigned Bs[256 * 17];   // [n][k], stride 17

    const int tid  = threadIdx.x;
    const int lane = tid & 31;
    const int wid  = tid >> 5;
    const int wr   = wid >> 2;          // warp row 0..1
    const int wc   = wid & 3;           // warp col 0..3 (= head)
    const int lr   = lane >> 2;         // 0..7
    const int lq   = lane & 3;          // 0..3
    const int row0 = blockIdx.x * 128;

    float c[4][8][4];
#pragma unroll
    for (int mt = 0; mt < 4; mt++)
#pragma unroll
        for (int nt = 0; nt < 8; nt++)
#pragma unroll
            for (int i = 0; i < 4; i++) c[mt][nt][i] = 0.f;

    const int a_r = tid >> 2;
    const int a_c = (tid & 3) * 4;

    float4 apf[2];
    float4 bpf[4];

#define LD_TILE(k0)                                                                   \
    do {                                                                              \
        _Pragma("unroll")                                                             \
        for (int i = 0; i < 2; i++) {                                                 \
            int r = row0 + a_r + i * 64;                                              \
            apf[i] = (r < NN) ? *reinterpret_cast<const float4*>(&A[(long)r * K + (k0) + a_c]) \
                              : make_float4(0.f, 0.f, 0.f, 0.f);                      \
        }                                                                             \
        _Pragma("unroll")                                                             \
        for (int i = 0; i < 4; i++) {                                                 \
            int idx = tid + i * 256;                                                  \
            int br = idx >> 6, bc = (idx & 63) * 4;                                   \
            bpf[i] = *reinterpret_cast<const float4*>(&B[(long)((k0) + br) * FD + bc]); \
        }                                                                             \
    } while (0)

#define ST_TILE()                                                                     \
    do {                                                                              \
        _Pragma("unroll")                                                             \
        for (int i = 0; i < 2; i++) {                                                 \
            int m = a_r + i * 64;                                                     \
            As[m * 17 + a_c + 0] = f2tf32(apf[i].x);                                  \
            As[m * 17 + a_c + 1] = f2tf32(apf[i].y);                                  \
            As[m * 17 + a_c + 2] = f2tf32(apf[i].z);                                  \
            As[m * 17 + a_c + 3] = f2tf32(apf[i].w);                                  \
        }                                                                             \
        _Pragma("unroll")                                                             \
        for (int i = 0; i < 4; i++) {                                                 \
            int idx = tid + i * 256;                                                  \
            int br = idx >> 6, bc = (idx & 63) * 4;                                   \
            Bs[(bc + 0) * 17 + br] = f2tf32(bpf[i].x);                                \
            Bs[(bc + 1) * 17 + br] = f2tf32(bpf[i].y);                                \
            Bs[(bc + 2) * 17 + br] = f2tf32(bpf[i].z);                                \
            Bs[(bc + 3) * 17 + br] = f2tf32(bpf[i].w);                                \
        }                                                                             \
    } while (0)

    LD_TILE(0);
    ST_TILE();
    __syncthreads();

    const int NT = K / 16;
    for (int t = 0; t < NT; t++) {
        if (t + 1 < NT) LD_TILE((t + 1) * 16);

#pragma unroll
        for (int ks = 0; ks < 2; ks++) {
            const int k = ks * 8;
            unsigned af[4][4], bf[8][2];
#pragma unroll
            for (int mt = 0; mt < 4; mt++) {
                int m = wr * 64 + mt * 16 + lr;
                af[mt][0] = As[m * 17 + k + lq];
                af[mt][1] = As[(m + 8) * 17 + k + lq];
                af[mt][2] = As[m * 17 + k + lq + 4];
                af[mt][3] = As[(m + 8) * 17 + k + lq + 4];
            }
#pragma unroll
            for (int nt = 0; nt < 8; nt++) {
                int n = wc * 64 + nt * 8 + lr;
                bf[nt][0] = Bs[n * 17 + k + lq];
                bf[nt][1] = Bs[n * 17 + k + lq + 4];
            }
#pragma unroll
            for (int mt = 0; mt < 4; mt++)
#pragma unroll
                for (int nt = 0; nt < 8; nt++)
                    mma_tf32(c[mt][nt], af[mt], bf[nt]);
        }
        __syncthreads();
        if (t + 1 < NT) {
            ST_TILE();
            __syncthreads();
        }
    }
#undef LD_TILE
#undef ST_TILE

    // Epilogue: write fp16 feature pairs + per-row el/er partials.
    float elp[8], erp[8];
#pragma unroll
    for (int h = 0; h < 8; h++) { elp[h] = 0.f; erp[h] = 0.f; }

#pragma unroll
    for (int mt = 0; mt < 4; mt++) {
        int r0 = row0 + wr * 64 + mt * 16 + lr;
#pragma unroll
        for (int nt = 0; nt < 8; nt++) {
            int col = wc * 64 + nt * 8 + 2 * lq;     // even feature index
            float al0 = al[col], al1 = al[col + 1];
            float ar0 = ar[col], ar1 = ar[col + 1];
            float v0 = c[mt][nt][0], v1 = c[mt][nt][1];
            float v2 = c[mt][nt][2], v3 = c[mt][nt][3];
            if (r0 < NN)
                g_featH[(long)r0 * 128 + (col >> 1)] = __floats2half2_rn(v0, v1);
            if (r0 + 8 < NN)
                g_featH[(long)(r0 + 8) * 128 + (col >> 1)] = __floats2half2_rn(v2, v3);
            elp[mt * 2]     += v0 * al0 + v1 * al1;
            erp[mt * 2]     += v0 * ar0 + v1 * ar1;
            elp[mt * 2 + 1] += v2 * al0 + v3 * al1;
            erp[mt * 2 + 1] += v2 * ar0 + v3 * ar1;
        }
    }
#pragma unroll
    for (int h = 0; h < 8; h++) {
        elp[h] += __shfl_xor_sync(0xffffffffu, elp[h], 1);
        elp[h] += __shfl_xor_sync(0xffffffffu, elp[h], 2);
        erp[h] += __shfl_xor_sync(0xffffffffu, erp[h], 1);
        erp[h] += __shfl_xor_sync(0xffffffffu, erp[h], 2);
    }
    if (lq == 0) {
#pragma unroll
        for (int mt = 0; mt < 4; mt++) {
            int r0 = row0 + wr * 64 + mt * 16 + lr;
            if (r0 < NN)     { g_el[r0 * 4 + wc] = elp[mt * 2];           g_er[r0 * 4 + wc] = erp[mt * 2]; }
            if (r0 + 8 < NN) { g_el[(r0 + 8) * 4 + wc] = elp[mt * 2 + 1]; g_er[(r0 + 8) * 4 + wc] = erp[mt * 2 + 1]; }
        }
    }
}

// ---------------- CSR build ----------------
__global__ void zero_cnt_kernel() {
    int i = blockIdx.x * blockDim.x + threadIdx.x;
    if (i < NN) g_cnt[i] = 0;
}
__global__ void count_deg_kernel(const int* __restrict__ ei) {
    int e = blockIdx.x * blockDim.x + threadIdx.x;
    if (e < NE) atomicAdd(&g_cnt[ei[NE + e]], 1);
}
__global__ __launch_bounds__(1024) void scan_kernel() {
    __shared__ int sh[1024];
    const int t = threadIdx.x;
    const int CH = 49;  // ceil(50000/1024)
    int b = t * CH;
    int e = min(b + CH, NN);
    int s = 0;
    for (int i = b; i < e; i++) s += g_cnt[i];
    sh[t] = s;
    __syncthreads();
    int own = s;
    for (int off = 1; off < 1024; off <<= 1) {
        int v = (t >= off) ? sh[t - off] : 0;
        __syncthreads();
        sh[t] += v;
        __syncthreads();
    }
    int run = sh[t] - own;
    for (int i = b; i < e; i++) {
        int c = g_cnt[i];
        g_rowptr[i] = run;
        run += c;
    }
    if (t == 1023) g_rowptr[NN] = sh[1023];
}
__global__ void scatter_kernel(const int* __restrict__ ei) {
    int e = blockIdx.x * blockDim.x + threadIdx.x;
    if (e < NE) {
        int s = ei[e];
        int d = ei[NE + e];
        int pos = g_rowptr[d] + atomicAdd(&g_cnt[d], 1);
        g_esrc[pos] = s;
    }
}

// ---------------- GAT edge softmax + aggregation: warp per dst node ----------------
// Lane owns feature pairs (k*64 + 2*lane, +1) for k=0..3; pair k belongs to head k.
// FINAL=false: write fp32 featB (relu(acc+bias)).
// FINAL=true : fuse head-mean + per-graph max pool (no feature write).
template <bool FINAL>
__global__ __launch_bounds__(256) void gat_aggregate_kernel(const float* __restrict__ bias,
                                                            float* __restrict__ out,
                                                            const int* __restrict__ graph_ids)
{
    int n    = blockIdx.x * 8 + (threadIdx.x >> 5);
    int lane = threadIdx.x & 31;
    if (n >= NN) return;
    int start = g_rowptr[n];
    int end   = g_rowptr[n + 1];

    float2 acc[4];
#pragma unroll
    for (int k = 0; k < 4; k++) acc[k] = make_float2(0.f, 0.f);

    if (end > start) {
        float4 er4 = *reinterpret_cast<const float4*>(&g_er[n * 4]);
        // fused pass: online softmax (running max m, rescaled running sum d)
        float m0 = -1e30f, m1 = -1e30f, m2 = -1e30f, m3 = -1e30f;
        float d0 = 0.f, d1 = 0.f, d2 = 0.f, d3 = 0.f;
        for (int i = start + lane; i < end; i += 32) {
            int s = g_esrc[i];
            float4 el4 = *reinterpret_cast<const float4*>(&g_el[s * 4]);
            float e0 = lrelu(el4.x + er4.x);
            float e1 = lrelu(el4.y + er4.y);
            float e2 = lrelu(el4.z + er4.z);
            float e3 = lrelu(el4.w + er4.w);
            float nm0 = fmaxf(m0, e0), nm1 = fmaxf(m1, e1);
            float nm2 = fmaxf(m2, e2), nm3 = fmaxf(m3, e3);
            d0 = d0 * __expf(m0 - nm0) + __expf(e0 - nm0);
            d1 = d1 * __expf(m1 - nm1) + __expf(e1 - nm1);
            d2 = d2 * __expf(m2 - nm2) + __expf(e2 - nm2);
            d3 = d3 * __expf(m3 - nm3) + __expf(e3 - nm3);
            m0 = nm0; m1 = nm1; m2 = nm2; m3 = nm3;
        }
#pragma unroll
        for (int o = 16; o > 0; o >>= 1) {
            float om0 = __shfl_xor_sync(0xffffffffu, m0, o);
            float om1 = __shfl_xor_sync(0xffffffffu, m1, o);
            float om2 = __shfl_xor_sync(0xffffffffu, m2, o);
            float om3 = __shfl_xor_sync(0xffffffffu, m3, o);
            float od0 = __shfl_xor_sync(0xffffffffu, d0, o);
            float od1 = __shfl_xor_sync(0xffffffffu, d1, o);
            float od2 = __shfl_xor_sync(0xffffffffu, d2, o);
            float od3 = __shfl_xor_sync(0xffffffffu, d3, o);
            float nm0 = fmaxf(m0, om0), nm1 = fmaxf(m1, om1);
            float nm2 = fmaxf(m2, om2), nm3 = fmaxf(m3, om3);
            d0 = d0 * __expf(m0 - nm0) + od0 * __expf(om0 - nm0);
            d1 = d1 * __expf(m1 - nm1) + od1 * __expf(om1 - nm1);
            d2 = d2 * __expf(m2 - nm2) + od2 * __expf(om2 - nm2);
            d3 = d3 * __expf(m3 - nm3) + od3 * __expf(om3 - nm3);
            m0 = nm0; m1 = nm1; m2 = nm2; m3 = nm3;
        }
        float i0 = 1.f / fmaxf(d0, 1e-9f);
        float i1 = 1.f / fmaxf(d1, 1e-9f);
        float i2 = 1.f / fmaxf(d2, 1e-9f);
        float i3 = 1.f / fmaxf(d3, 1e-9f);
        // pass C: weighted fp16 gather-sum, software-pipelined 1 deep.
        int s_cur = g_esrc[start];
        float4 el_cur = *reinterpret_cast<const float4*>(&g_el[s_cur * 4]);
        for (int i = start; i < end; i++) {
            int s_nxt = 0;
            float4 el_nxt = el_cur;
            if (i + 1 < end) {
                s_nxt = g_esrc[i + 1];
                el_nxt = *reinterpret_cast<const float4*>(&g_el[s_nxt * 4]);
            }
            float a0 = __expf(lrelu(el_cur.x + er4.x) - m0) * i0;
            float a1 = __expf(lrelu(el_cur.y + er4.y) - m1) * i1;
            float a2 = __expf(lrelu(el_cur.z + er4.z) - m2) * i2;
            float a3 = __expf(lrelu(el_cur.w + er4.w) - m3) * i3;
            const __half2* fr = &g_featH[(long)s_cur * 128];
            float2 f0 = __half22float2(fr[lane]);
            float2 f1 = __half22float2(fr[32 + lane]);
            float2 f2 = __half22float2(fr[64 + lane]);
            float2 f3 = __half22float2(fr[96 + lane]);
            acc[0].x = fmaf(a0, f0.x, acc[0].x); acc[0].y = fmaf(a0, f0.y, acc[0].y);
            acc[1].x = fmaf(a1, f1.x, acc[1].x); acc[1].y = fmaf(a1, f1.y, acc[1].y);
            acc[2].x = fmaf(a2, f2.x, acc[2].x); acc[2].y = fmaf(a2, f2.y, acc[2].y);
            acc[3].x = fmaf(a3, f3.x, acc[3].x); acc[3].y = fmaf(a3, f3.y, acc[3].y);
            s_cur = s_nxt;
            el_cur = el_nxt;
        }
    }

    if (!FINAL) {
#pragma unroll
        for (int k = 0; k < 4; k++) {
            int f = k * 64 + 2 * lane;
            float v0 = acc[k].x + bias[f];
            float v1 = acc[k].y + bias[f + 1];
            v0 = v0 > 0.f ? v0 : 0.f;
            v1 = v1 > 0.f ? v1 : 0.f;
            *reinterpret_cast<float2*>(&out[(long)n * FD + f]) = make_float2(v0, v1);
        }
    } else {
        float hx = 0.f, hy = 0.f;
#pragma unroll
        for (int k = 0; k < 4; k++) {
            int f = k * 64 + 2 * lane;
            float v0 = acc[k].x + bias[f];
            float v1 = acc[k].y + bias[f + 1];
            hx += v0 > 0.f ? v0 : 0.f;
            hy += v1 > 0.f ? v1 : 0.f;
        }
        int g = graph_ids[n];
        atomicMax(&g_pool[g * HID + 2 * lane],     f2ord(0.25f * hx));
        atomicMax(&g_pool[g * HID + 2 * lane + 1], f2ord(0.25f * hy));
    }
}

// ---------------- pooling / classifier ----------------
__global__ void pool_init_kernel() {
    int i = blockIdx.x * blockDim.x + threadIdx.x;
    if (i < NG * HID) g_pool[i] = f2ord(-3.0e38f);
}
__global__ void classifier_kernel(const float* __restrict__ Wc,
                                  const float* __restrict__ bc,
                                  float* __restrict__ out)
{
    int t = blockIdx.x * blockDim.x + threadIdx.x;
    if (t >= NG * NC) return;
    int g = t / NC;
    int c = t % NC;
    float s = bc[c];
#pragma unroll 8
    for (int d = 0; d < HID; d++)
        s = fmaf(ord2f(g_pool[g * HID + d]), Wc[d * NC + c], s);
    out[t] = s;
}

// ---------------- host launcher ----------------
extern "C" void kernel_launch(void* const* d_in, const int* in_sizes, int n_in,
                              void* d_out, int out_size)
{
    const float* h   = (const float*)d_in[0];
    const float* W1  = (const float*)d_in[1];
    const float* al1 = (const float*)d_in[2];
    const float* ar1 = (const float*)d_in[3];
    const float* b1  = (const float*)d_in[4];
    const float* W2  = (const float*)d_in[5];
    const float* al2 = (const float*)d_in[6];
    const float* ar2 = (const float*)d_in[7];
    const float* b2  = (const float*)d_in[8];
    const float* Wc  = (const float*)d_in[9];
    const float* bc  = (const float*)d_in[10];
    const int* ei    = (const int*)d_in[11];
    const int* gid   = (const int*)d_in[12];
    float* out = (float*)d_out;

    void* pB = nullptr;
    cudaGetSymbolAddress(&pB, g_featB);
    float* featB = (float*)pB;

    const int warp_blocks = (NN + 7) / 8;
    const int gemm_blocks = (NN + 127) / 128;

    // CSR build (layer-independent)
    zero_cnt_kernel<<<(NN + 255) / 256, 256>>>();
    count_deg_kernel<<<(NE + 255) / 256, 256>>>(ei);
    scan_kernel<<<1, 1024>>>();
    zero_cnt_kernel<<<(NN + 255) / 256, 256>>>();
    scatter_kernel<<<(NE + 255) / 256, 256>>>(ei);
    pool_init_kernel<<<(NG * HID + 255) / 256, 256>>>();

    // Layer 1: fused tf32 GEMM (fp16 feature table + el/er)
    gemm_attn_kernel<IND><<<gemm_blocks, 256>>>(h, W1, al1, ar1);
    gat_aggregate_kernel<false><<<warp_blocks, 256>>>(b1, featB, gid);

    // Layer 2
    gemm_attn_kernel<FD><<<gemm_blocks, 256>>>(featB, W2, al2, ar2);
    gat_aggregate_kernel<true><<<warp_blocks, 256>>>(b2, nullptr, gid);

    // Classifier
    classifier_kernel<<<(NG * NC + 255) / 256, 256>>>(Wc, bc, out);
}

// round 5
// speedup vs baseline: 1.0445x; 1.0445x over previous
#include <cuda_runtime.h>
#include <cuda_fp16.h>

// Problem constants (shape-specialized)
#define NN 50000       // nodes
#define NE 800000      // edges
#define IND 128        // input dim
#define FD  256        // HEADS*HID
#define HID 64
#define NG  64         // graphs
#define NC  10         // classes
#define SLOPE 0.2f

// ---------------- device scratch (no allocations allowed) ----------------
__device__ float    g_featB[NN * FD];     // aggregated layer-1 output (GEMM2 input, fp32)
__device__ __half2  g_featH[NN * FD / 2]; // projected features, fp16 pairs (gather table)
__device__ float    g_el[NN * 4];
__device__ float    g_er[NN * 4];
__device__ int      g_rowptr[NN + 1];
__device__ int      g_cnt[NN];
__device__ int      g_esrc[NE];           // src node id, sorted by dst (CSR)
__device__ unsigned g_pool[NG * HID];     // ordered-uint max-pool accumulator

// ---------------- helpers ----------------
__device__ __forceinline__ unsigned f2ord(float f) {
    unsigned u = __float_as_uint(f);
    return (u >> 31) ? ~u : (u | 0x80000000u);
}
__device__ __forceinline__ float ord2f(unsigned u) {
    return (u >> 31) ? __uint_as_float(u & 0x7fffffffu) : __uint_as_float(~u);
}
__device__ __forceinline__ float lrelu(float x) { return x > 0.f ? x : SLOPE * x; }

__device__ __forceinline__ unsigned f2tf32(float x) {
    unsigned r;
    asm("cvt.rna.tf32.f32 %0, %1;" : "=r"(r) : "f"(x));
    return r;
}
__device__ __forceinline__ void mma_tf32(float c[4], const unsigned a[4], const unsigned b[2]) {
    asm volatile(
        "mma.sync.aligned.m16n8k8.row.col.f32.tf32.tf32.f32 "
        "{%0,%1,%2,%3}, {%4,%5,%6,%7}, {%8,%9}, {%0,%1,%2,%3};"
        : "+f"(c[0]), "+f"(c[1]), "+f"(c[2]), "+f"(c[3])
        : "r"(a[0]), "r"(a[1]), "r"(a[2]), "r"(a[3]), "r"(b[0]), "r"(b[1]));
}

// ---------------- fused tf32 GEMM + attention coefficients ----------------
// feat = A[M,K] @ B[K,256] (tf32, fp32 acc). Output written ONLY as fp16 pairs
// to g_featH; el/er written fp32. Block tile 128x256 (full width), BK=16,
// 8 warps of 64x64; warp-col == head.
template <int K>
__global__ __launch_bounds__(256) void gemm_attn_kernel(const float* __restrict__ A,
                                                        const float* __restrict__ B,
                                                        const float* __restrict__ al,
                                                        const float* __restrict__ ar)
{
    __shared__ unsigned As[128 * 17];   // [m][k], stride 17
    __shared__ unsigned Bs[256 * 17];   // [n][k], stride 17

    const int tid  = threadIdx.x;
    const int lane = tid & 31;
    const int wid  = tid >> 5;
    const int wr   = wid >> 2;          // warp row 0..1
    const int wc   = wid & 3;           // warp col 0..3 (= head)
    const int lr   = lane >> 2;         // 0..7
    const int lq   = lane & 3;          // 0..3
    const int row0 = blockIdx.x * 128;

    float c[4][8][4];
#pragma unroll
    for (int mt = 0; mt < 4; mt++)
#pragma unroll
        for (int nt = 0; nt < 8; nt++)
#pragma unroll
            for (int i = 0; i < 4; i++) c[mt][nt][i] = 0.f;

    const int a_r = tid >> 2;
    const int a_c = (tid & 3) * 4;

    float4 apf[2];
    float4 bpf[4];

#define LD_TILE(k0)                                                                   \
    do {                                                                              \
        _Pragma("unroll")                                                             \
        for (int i = 0; i < 2; i++) {                                                 \
            int r = row0 + a_r + i * 64;                                              \
            apf[i] = (r < NN) ? *reinterpret_cast<const float4*>(&A[(long)r * K + (k0) + a_c]) \
                              : make_float4(0.f, 0.f, 0.f, 0.f);                      \
        }                                                                             \
        _Pragma("unroll")                                                             \
        for (int i = 0; i < 4; i++) {                                                 \
            int idx = tid + i * 256;                                                  \
            int br = idx >> 6, bc = (idx & 63) * 4;                                   \
            bpf[i] = *reinterpret_cast<const float4*>(&B[(long)((k0) + br) * FD + bc]); \
        }                                                                             \
    } while (0)

#define ST_TILE()                                                                     \
    do {                                                                              \
        _Pragma("unroll")                                                             \
        for (int i = 0; i < 2; i++) {                                                 \
            int m = a_r + i * 64;                                                     \
            As[m * 17 + a_c + 0] = f2tf32(apf[i].x);                                  \
            As[m * 17 + a_c + 1] = f2tf32(apf[i].y);                                  \
            As[m * 17 + a_c + 2] = f2tf32(apf[i].z);                                  \
            As[m * 17 + a_c + 3] = f2tf32(apf[i].w);                                  \
        }                                                                             \
        _Pragma("unroll")                                                             \
        for (int i = 0; i < 4; i++) {                                                 \
            int idx = tid + i * 256;                                                  \
            int br = idx >> 6, bc = (idx & 63) * 4;                                   \
            Bs[(bc + 0) * 17 + br] = f2tf32(bpf[i].x);                                \
            Bs[(bc + 1) * 17 + br] = f2tf32(bpf[i].y);                                \
            Bs[(bc + 2) * 17 + br] = f2tf32(bpf[i].z);                                \
            Bs[(bc + 3) * 17 + br] = f2tf32(bpf[i].w);                                \
        }                                                                             \
    } while (0)

    LD_TILE(0);
    ST_TILE();
    __syncthreads();

    const int NT = K / 16;
    for (int t = 0; t < NT; t++) {
        if (t + 1 < NT) LD_TILE((t + 1) * 16);

#pragma unroll
        for (int ks = 0; ks < 2; ks++) {
            const int k = ks * 8;
            unsigned af[4][4], bf[8][2];
#pragma unroll
            for (int mt = 0; mt < 4; mt++) {
                int m = wr * 64 + mt * 16 + lr;
                af[mt][0] = As[m * 17 + k + lq];
                af[mt][1] = As[(m + 8) * 17 + k + lq];
                af[mt][2] = As[m * 17 + k + lq + 4];
                af[mt][3] = As[(m + 8) * 17 + k + lq + 4];
            }
#pragma unroll
            for (int nt = 0; nt < 8; nt++) {
                int n = wc * 64 + nt * 8 + lr;
                bf[nt][0] = Bs[n * 17 + k + lq];
                bf[nt][1] = Bs[n * 17 + k + lq + 4];
            }
#pragma unroll
            for (int mt = 0; mt < 4; mt++)
#pragma unroll
                for (int nt = 0; nt < 8; nt++)
                    mma_tf32(c[mt][nt], af[mt], bf[nt]);
        }
        __syncthreads();
        if (t + 1 < NT) {
            ST_TILE();
            __syncthreads();
        }
    }
#undef LD_TILE
#undef ST_TILE

    // Epilogue: write fp16 feature pairs + per-row el/er partials.
    float elp[8], erp[8];
#pragma unroll
    for (int h = 0; h < 8; h++) { elp[h] = 0.f; erp[h] = 0.f; }

#pragma unroll
    for (int mt = 0; mt < 4; mt++) {
        int r0 = row0 + wr * 64 + mt * 16 + lr;
#pragma unroll
        for (int nt = 0; nt < 8; nt++) {
            int col = wc * 64 + nt * 8 + 2 * lq;     // even feature index
            float al0 = al[col], al1 = al[col + 1];
            float ar0 = ar[col], ar1 = ar[col + 1];
            float v0 = c[mt][nt][0], v1 = c[mt][nt][1];
            float v2 = c[mt][nt][2], v3 = c[mt][nt][3];
            if (r0 < NN)
                g_featH[(long)r0 * 128 + (col >> 1)] = __floats2half2_rn(v0, v1);
            if (r0 + 8 < NN)
                g_featH[(long)(r0 + 8) * 128 + (col >> 1)] = __floats2half2_rn(v2, v3);
            elp[mt * 2]     += v0 * al0 + v1 * al1;
            erp[mt * 2]     += v0 * ar0 + v1 * ar1;
            elp[mt * 2 + 1] += v2 * al0 + v3 * al1;
            erp[mt * 2 + 1] += v2 * ar0 + v3 * ar1;
        }
    }
#pragma unroll
    for (int h = 0; h < 8; h++) {
        elp[h] += __shfl_xor_sync(0xffffffffu, elp[h], 1);
        elp[h] += __shfl_xor_sync(0xffffffffu, elp[h], 2);
        erp[h] += __shfl_xor_sync(0xffffffffu, erp[h], 1);
        erp[h] += __shfl_xor_sync(0xffffffffu, erp[h], 2);
    }
    if (lq == 0) {
#pragma unroll
        for (int mt = 0; mt < 4; mt++) {
            int r0 = row0 + wr * 64 + mt * 16 + lr;
            if (r0 < NN)     { g_el[r0 * 4 + wc] = elp[mt * 2];           g_er[r0 * 4 + wc] = erp[mt * 2]; }
            if (r0 + 8 < NN) { g_el[(r0 + 8) * 4 + wc] = elp[mt * 2 + 1]; g_er[(r0 + 8) * 4 + wc] = erp[mt * 2 + 1]; }
        }
    }
}

// ---------------- CSR build ----------------
__global__ void zero_cnt_kernel() {
    int i = blockIdx.x * blockDim.x + threadIdx.x;
    if (i < NN) g_cnt[i] = 0;
}
__global__ void count_deg_kernel(const int* __restrict__ ei) {
    int e = blockIdx.x * blockDim.x + threadIdx.x;
    if (e < NE) atomicAdd(&g_cnt[ei[NE + e]], 1);
}
__global__ __launch_bounds__(1024) void scan_kernel() {
    __shared__ int sh[1024];
    const int t = threadIdx.x;
    const int CH = 49;  // ceil(50000/1024)
    int b = t * CH;
    int e = min(b + CH, NN);
    int s = 0;
    for (int i = b; i < e; i++) s += g_cnt[i];
    sh[t] = s;
    __syncthreads();
    int own = s;
    for (int off = 1; off < 1024; off <<= 1) {
        int v = (t >= off) ? sh[t - off] : 0;
        __syncthreads();
        sh[t] += v;
        __syncthreads();
    }
    int run = sh[t] - own;
    for (int i = b; i < e; i++) {
        int c = g_cnt[i];
        g_rowptr[i] = run;
        run += c;
    }
    if (t == 1023) g_rowptr[NN] = sh[1023];
}
__global__ void scatter_kernel(const int* __restrict__ ei) {
    int e = blockIdx.x * blockDim.x + threadIdx.x;
    if (e < NE) {
        int s = ei[e];
        int d = ei[NE + e];
        int pos = g_rowptr[d] + atomicAdd(&g_cnt[d], 1);
        g_esrc[pos] = s;
    }
}

// ---------------- GAT edge softmax + aggregation: warp per dst node ----------------
// Lane owns feature pairs (k*64 + 2*lane, +1) for k=0..3; pair k belongs to head k.
// Two passes: A) strided per-head max (no exp).  B') serial fused pass
// accumulating BOTH denom and weighted feature sum (4 exps/edge total);
// normalize once at the end.
// FINAL=false: write fp32 featB (relu(acc+bias)).
// FINAL=true : fuse head-mean + per-graph max pool (no feature write).
template <bool FINAL>
__global__ __launch_bounds__(256) void gat_aggregate_kernel(const float* __restrict__ bias,
                                                            float* __restrict__ out,
                                                            const int* __restrict__ graph_ids)
{
    int n    = blockIdx.x * 8 + (threadIdx.x >> 5);
    int lane = threadIdx.x & 31;
    if (n >= NN) return;
    int start = g_rowptr[n];
    int end   = g_rowptr[n + 1];

    float2 acc[4];
#pragma unroll
    for (int k = 0; k < 4; k++) acc[k] = make_float2(0.f, 0.f);

    if (end > start) {
        float4 er4 = *reinterpret_cast<const float4*>(&g_er[n * 4]);
        // pass A: strided per-head max of leaky_relu(el+er) — no exp.
        float m0 = -1e30f, m1 = -1e30f, m2 = -1e30f, m3 = -1e30f;
        for (int i = start + lane; i < end; i += 32) {
            int s = g_esrc[i];
            float4 el4 = *reinterpret_cast<const float4*>(&g_el[s * 4]);
            m0 = fmaxf(m0, lrelu(el4.x + er4.x));
            m1 = fmaxf(m1, lrelu(el4.y + er4.y));
            m2 = fmaxf(m2, lrelu(el4.z + er4.z));
            m3 = fmaxf(m3, lrelu(el4.w + er4.w));
        }
#pragma unroll
        for (int o = 16; o > 0; o >>= 1) {
            m0 = fmaxf(m0, __shfl_xor_sync(0xffffffffu, m0, o));
            m1 = fmaxf(m1, __shfl_xor_sync(0xffffffffu, m1, o));
            m2 = fmaxf(m2, __shfl_xor_sync(0xffffffffu, m2, o));
            m3 = fmaxf(m3, __shfl_xor_sync(0xffffffffu, m3, o));
        }
        // pass B': serial fused denom + weighted gather-sum, pipelined 1 deep.
        float d0 = 0.f, d1 = 0.f, d2 = 0.f, d3 = 0.f;
        int s_cur = g_esrc[start];
        float4 el_cur = *reinterpret_cast<const float4*>(&g_el[s_cur * 4]);
        for (int i = start; i < end; i++) {
            int s_nxt = 0;
            float4 el_nxt = el_cur;
            if (i + 1 < end) {
                s_nxt = g_esrc[i + 1];
                el_nxt = *reinterpret_cast<const float4*>(&g_el[s_nxt * 4]);
            }
            float w0 = __expf(lrelu(el_cur.x + er4.x) - m0);
            float w1 = __expf(lrelu(el_cur.y + er4.y) - m1);
            float w2 = __expf(lrelu(el_cur.z + er4.z) - m2);
            float w3 = __expf(lrelu(el_cur.w + er4.w) - m3);
            d0 += w0; d1 += w1; d2 += w2; d3 += w3;
            const __half2* fr = &g_featH[(long)s_cur * 128];
            float2 f0 = __half22float2(fr[lane]);
            float2 f1 = __half22float2(fr[32 + lane]);
            float2 f2 = __half22float2(fr[64 + lane]);
            float2 f3 = __half22float2(fr[96 + lane]);
            acc[0].x = fmaf(w0, f0.x, acc[0].x); acc[0].y = fmaf(w0, f0.y, acc[0].y);
            acc[1].x = fmaf(w1, f1.x, acc[1].x); acc[1].y = fmaf(w1, f1.y, acc[1].y);
            acc[2].x = fmaf(w2, f2.x, acc[2].x); acc[2].y = fmaf(w2, f2.y, acc[2].y);
            acc[3].x = fmaf(w3, f3.x, acc[3].x); acc[3].y = fmaf(w3, f3.y, acc[3].y);
            s_cur = s_nxt;
            el_cur = el_nxt;
        }
        float i0 = 1.f / fmaxf(d0, 1e-9f);
        float i1 = 1.f / fmaxf(d1, 1e-9f);
        float i2 = 1.f / fmaxf(d2, 1e-9f);
        float i3 = 1.f / fmaxf(d3, 1e-9f);
        acc[0].x *= i0; acc[0].y *= i0;
        acc[1].x *= i1; acc[1].y *= i1;
        acc[2].x *= i2; acc[2].y *= i2;
        acc[3].x *= i3; acc[3].y *= i3;
    }

    if (!FINAL) {
#pragma unroll
        for (int k = 0; k < 4; k++) {
            int f = k * 64 + 2 * lane;
            float v0 = acc[k].x + bias[f];
            float v1 = acc[k].y + bias[f + 1];
            v0 = v0 > 0.f ? v0 : 0.f;
            v1 = v1 > 0.f ? v1 : 0.f;
            *reinterpret_cast<float2*>(&out[(long)n * FD + f]) = make_float2(v0, v1);
        }
    } else {
        float hx = 0.f, hy = 0.f;
#pragma unroll
        for (int k = 0; k < 4; k++) {
            int f = k * 64 + 2 * lane;
            float v0 = acc[k].x + bias[f];
            float v1 = acc[k].y + bias[f + 1];
            hx += v0 > 0.f ? v0 : 0.f;
            hy += v1 > 0.f ? v1 : 0.f;
        }
        int g = graph_ids[n];
        atomicMax(&g_pool[g * HID + 2 * lane],     f2ord(0.25f * hx));
        atomicMax(&g_pool[g * HID + 2 * lane + 1], f2ord(0.25f * hy));
    }
}

// ---------------- pooling / classifier ----------------
__global__ void pool_init_kernel() {
    int i = blockIdx.x * blockDim.x + threadIdx.x;
    if (i < NG * HID) g_pool[i] = f2ord(-3.0e38f);
}
__global__ void classifier_kernel(const float* __restrict__ Wc,
                                  const float* __restrict__ bc,
                                  float* __restrict__ out)
{
    int t = blockIdx.x * blockDim.x + threadIdx.x;
    if (t >= NG * NC) return;
    int g = t / NC;
    int c = t % NC;
    float s = bc[c];
#pragma unroll 8
    for (int d = 0; d < HID; d++)
        s = fmaf(ord2f(g_pool[g * HID + d]), Wc[d * NC + c], s);
    out[t] = s;
}

// ---------------- host launcher ----------------
extern "C" void kernel_launch(void* const* d_in, const int* in_sizes, int n_in,
                              void* d_out, int out_size)
{
    const float* h   = (const float*)d_in[0];
    const float* W1  = (const float*)d_in[1];
    const float* al1 = (const float*)d_in[2];
    const float* ar1 = (const float*)d_in[3];
    const float* b1  = (const float*)d_in[4];
    const float* W2  = (const float*)d_in[5];
    const float* al2 = (const float*)d_in[6];
    const float* ar2 = (const float*)d_in[7];
    const float* b2  = (const float*)d_in[8];
    const float* Wc  = (const float*)d_in[9];
    const float* bc  = (const float*)d_in[10];
    const int* ei    = (const int*)d_in[11];
    const int* gid   = (const int*)d_in[12];
    float* out = (float*)d_out;

    void* pB = nullptr;
    cudaGetSymbolAddress(&pB, g_featB);
    float* featB = (float*)pB;

    const int warp_blocks = (NN + 7) / 8;
    const int gemm_blocks = (NN + 127) / 128;

    // CSR build (layer-independent)
    zero_cnt_kernel<<<(NN + 255) / 256, 256>>>();
    count_deg_kernel<<<(NE + 255) / 256, 256>>>(ei);
    scan_kernel<<<1, 1024>>>();
    zero_cnt_kernel<<<(NN + 255) / 256, 256>>>();
    scatter_kernel<<<(NE + 255) / 256, 256>>>(ei);
    pool_init_kernel<<<(NG * HID + 255) / 256, 256>>>();

    // Layer 1: fused tf32 GEMM (fp16 feature table + el/er)
    gemm_attn_kernel<IND><<<gemm_blocks, 256>>>(h, W1, al1, ar1);
    gat_aggregate_kernel<false><<<warp_blocks, 256>>>(b1, featB, gid);

    // Layer 2
    gemm_attn_kernel<FD><<<gemm_blocks, 256>>>(featB, W2, al2, ar2);
    gat_aggregate_kernel<true><<<warp_blocks, 256>>>(b2, nullptr, gid);

    // Classifier
    classifier_kernel<<<(NG * NC + 255) / 256, 256>>>(Wc, bc, out);
}